// round 1
// baseline (speedup 1.0000x reference)
#include <cuda_runtime.h>
#include <math.h>

#define NB 8
#define SEQ 2048
#define DIN 512
#define DK 64
#define MTOT (NB*SEQ)   // 16384

// Scratch for projected Q, K, V (4 MB each) — __device__ globals, no allocation.
__device__ float g_q[MTOT * DK];
__device__ float g_k[MTOT * DK];
__device__ float g_v[MTOT * DK];

// ---------------------------------------------------------------------------
// Projection GEMM: Y[M,64] = X[M,512] @ W[512,64] + bias
// Block computes a 64x64 output tile; 256 threads, 4x4 micro-tile per thread.
// ---------------------------------------------------------------------------
__global__ __launch_bounds__(256) void proj_kernel(
    const float* __restrict__ X, const float* __restrict__ W,
    const float* __restrict__ bias, float* __restrict__ Y)
{
    __shared__ float Xs[64][33];   // [row][k] for a 32-wide K chunk (+pad)
    __shared__ float Ws[32][65];   // [k][col] (+pad)

    const int tid = threadIdx.x;
    const int ty = tid >> 4;       // 0..15 -> row group
    const int tx = tid & 15;       // 0..15 -> col group
    const int r0 = blockIdx.x * 64;

    float acc[4][4];
#pragma unroll
    for (int i = 0; i < 4; i++)
#pragma unroll
        for (int j = 0; j < 4; j++) acc[i][j] = 0.0f;

    for (int kc = 0; kc < DIN; kc += 32) {
        // Load X tile: 64 rows x 32 cols = 512 float4
        for (int v = tid; v < 512; v += 256) {
            int row = v >> 3;          // 8 float4 per row
            int c4  = v & 7;
            float4 x = *(const float4*)&X[(size_t)(r0 + row) * DIN + kc + c4 * 4];
            Xs[row][c4*4+0] = x.x; Xs[row][c4*4+1] = x.y;
            Xs[row][c4*4+2] = x.z; Xs[row][c4*4+3] = x.w;
        }
        // Load W tile: 32 rows x 64 cols = 512 float4
        for (int v = tid; v < 512; v += 256) {
            int row = v >> 4;          // 16 float4 per row
            int c4  = v & 15;
            float4 w = *(const float4*)&W[(size_t)(kc + row) * DK + c4 * 4];
            Ws[row][c4*4+0] = w.x; Ws[row][c4*4+1] = w.y;
            Ws[row][c4*4+2] = w.z; Ws[row][c4*4+3] = w.w;
        }
        __syncthreads();

#pragma unroll
        for (int k = 0; k < 32; k++) {
            float a[4], b[4];
#pragma unroll
            for (int i = 0; i < 4; i++) a[i] = Xs[ty*4 + i][k];
#pragma unroll
            for (int j = 0; j < 4; j++) b[j] = Ws[k][tx*4 + j];
#pragma unroll
            for (int i = 0; i < 4; i++)
#pragma unroll
                for (int j = 0; j < 4; j++)
                    acc[i][j] = fmaf(a[i], b[j], acc[i][j]);
        }
        __syncthreads();
    }

#pragma unroll
    for (int i = 0; i < 4; i++) {
        int row = r0 + ty*4 + i;
#pragma unroll
        for (int j = 0; j < 4; j++) {
            int col = tx*4 + j;
            Y[(size_t)row * DK + col] = acc[i][j] + bias[col];
        }
    }
}

// ---------------------------------------------------------------------------
// Flash attention: per block, one (batch, 64-query tile). Online softmax over
// 32 key tiles of 64. 256 threads, 4x4 micro-tiles for both GEMMs.
// Dynamic smem: Qs, Ks, Vs, Ps each 64x65 floats = 66,560 bytes total.
// ---------------------------------------------------------------------------
#define TPAD 65
__global__ __launch_bounds__(256) void attn_kernel(float* __restrict__ out)
{
    extern __shared__ float sm[];
    float (*Qs)[TPAD] = (float (*)[TPAD])(sm);
    float (*Ks)[TPAD] = (float (*)[TPAD])(sm + 64*TPAD);
    float (*Vs)[TPAD] = (float (*)[TPAD])(sm + 2*64*TPAD);
    float (*Ps)[TPAD] = (float (*)[TPAD])(sm + 3*64*TPAD);

    const int tid = threadIdx.x;
    const int ty  = tid >> 4;
    const int tx  = tid & 15;
    const int b   = blockIdx.y;
    const int qt  = blockIdx.x;
    const float scale = 0.125f;   // 1/sqrt(64)

    // Load Q tile (scale folded in)
    const int qbase = (b * SEQ + qt * 64) * DK;
    for (int v = tid; v < 1024; v += 256) {   // 1024 float4
        int row = v >> 4;
        int c4  = v & 15;
        float4 x = *(const float4*)&g_q[qbase + row * DK + c4 * 4];
        Qs[row][c4*4+0] = x.x * scale; Qs[row][c4*4+1] = x.y * scale;
        Qs[row][c4*4+2] = x.z * scale; Qs[row][c4*4+3] = x.w * scale;
    }

    float m[4], l[4], o[4][4];
#pragma unroll
    for (int i = 0; i < 4; i++) {
        m[i] = -1e30f; l[i] = 0.0f;
#pragma unroll
        for (int j = 0; j < 4; j++) o[i][j] = 0.0f;
    }

    for (int kt = 0; kt < SEQ / 64; kt++) {
        __syncthreads();   // previous iteration's PV readers done
        const int kbase = (b * SEQ + kt * 64) * DK;
        for (int v = tid; v < 2048; v += 256) {
            int local = v & 1023;
            int row = local >> 4;
            int c4  = local & 15;
            if (v < 1024) {
                float4 x = *(const float4*)&g_k[kbase + row * DK + c4 * 4];
                Ks[row][c4*4+0] = x.x; Ks[row][c4*4+1] = x.y;
                Ks[row][c4*4+2] = x.z; Ks[row][c4*4+3] = x.w;
            } else {
                float4 x = *(const float4*)&g_v[kbase + row * DK + c4 * 4];
                Vs[row][c4*4+0] = x.x; Vs[row][c4*4+1] = x.y;
                Vs[row][c4*4+2] = x.z; Vs[row][c4*4+3] = x.w;
            }
        }
        __syncthreads();

        // S = Q @ K^T  (scaled)
        float s[4][4];
#pragma unroll
        for (int i = 0; i < 4; i++)
#pragma unroll
            for (int j = 0; j < 4; j++) s[i][j] = 0.0f;
#pragma unroll
        for (int k = 0; k < 64; k++) {
            float a[4], bb[4];
#pragma unroll
            for (int i = 0; i < 4; i++) a[i]  = Qs[ty*4 + i][k];
#pragma unroll
            for (int j = 0; j < 4; j++) bb[j] = Ks[tx*4 + j][k];
#pragma unroll
            for (int i = 0; i < 4; i++)
#pragma unroll
                for (int j = 0; j < 4; j++)
                    s[i][j] = fmaf(a[i], bb[j], s[i][j]);
        }

        // Online softmax per row (row stats reduced across the 16 tx lanes)
#pragma unroll
        for (int i = 0; i < 4; i++) {
            float mx = fmaxf(fmaxf(s[i][0], s[i][1]), fmaxf(s[i][2], s[i][3]));
#pragma unroll
            for (int off = 8; off >= 1; off >>= 1)
                mx = fmaxf(mx, __shfl_xor_sync(0xffffffffu, mx, off, 16));
            float mnew = fmaxf(m[i], mx);
            float p[4], rs = 0.0f;
#pragma unroll
            for (int j = 0; j < 4; j++) {
                p[j] = __expf(s[i][j] - mnew);
                rs += p[j];
            }
#pragma unroll
            for (int off = 8; off >= 1; off >>= 1)
                rs += __shfl_xor_sync(0xffffffffu, rs, off, 16);
            float alpha = __expf(m[i] - mnew);
            l[i] = l[i] * alpha + rs;
            m[i] = mnew;
#pragma unroll
            for (int j = 0; j < 4; j++) {
                o[i][j] *= alpha;
                Ps[ty*4 + i][tx*4 + j] = p[j];
            }
        }
        __syncthreads();

        // O += P @ V
#pragma unroll
        for (int k = 0; k < 64; k++) {
            float a[4], bb[4];
#pragma unroll
            for (int i = 0; i < 4; i++) a[i]  = Ps[ty*4 + i][k];
#pragma unroll
            for (int j = 0; j < 4; j++) bb[j] = Vs[k][tx*4 + j];
#pragma unroll
            for (int i = 0; i < 4; i++)
#pragma unroll
                for (int j = 0; j < 4; j++)
                    o[i][j] = fmaf(a[i], bb[j], o[i][j]);
        }
    }

    const int obase = (b * SEQ + qt * 64) * DK;
#pragma unroll
    for (int i = 0; i < 4; i++) {
        float inv = 1.0f / l[i];
#pragma unroll
        for (int j = 0; j < 4; j++)
            out[obase + (ty*4 + i) * DK + tx*4 + j] = o[i][j] * inv;
    }
}

// ---------------------------------------------------------------------------
extern "C" void kernel_launch(void* const* d_in, const int* in_sizes, int n_in,
                              void* d_out, int out_size)
{
    const float* q_in = (const float*)d_in[0];
    const float* k_in = (const float*)d_in[1];
    const float* v_in = (const float*)d_in[2];
    const float* Wq   = (const float*)d_in[3];
    const float* bq   = (const float*)d_in[4];
    const float* Wk   = (const float*)d_in[5];
    const float* bk   = (const float*)d_in[6];
    const float* Wv   = (const float*)d_in[7];
    const float* bv   = (const float*)d_in[8];
    float* out = (float*)d_out;

    float *qp, *kp, *vp;
    cudaGetSymbolAddress((void**)&qp, g_q);
    cudaGetSymbolAddress((void**)&kp, g_k);
    cudaGetSymbolAddress((void**)&vp, g_v);

    // Projections
    dim3 pgrid(MTOT / 64);
    proj_kernel<<<pgrid, 256>>>(q_in, Wq, bq, qp);
    proj_kernel<<<pgrid, 256>>>(k_in, Wk, bk, kp);
    proj_kernel<<<pgrid, 256>>>(v_in, Wv, bv, vp);

    // Attention
    static int smem_set = 0;
    const int smem_bytes = 4 * 64 * TPAD * sizeof(float);  // 66,560
    if (!smem_set) {
        cudaFuncSetAttribute(attn_kernel,
                             cudaFuncAttributeMaxDynamicSharedMemorySize,
                             smem_bytes);
        smem_set = 1;
    }
    dim3 agrid(SEQ / 64, NB);
    attn_kernel<<<agrid, 256, smem_bytes>>>(out);
}

// round 6
// speedup vs baseline: 2.1135x; 2.1135x over previous
#include <cuda_runtime.h>

#define NB  8
#define SEQ 2048
#define DIN 512
#define DK  64
#define MTOT (NB*SEQ)   // 16384

// Projected Q, K, V scratch (4 MB each) — __device__ globals, no allocation.
__device__ float g_q[MTOT * DK];
__device__ float g_k[MTOT * DK];
__device__ float g_v[MTOT * DK];

// ---------------------------------------------------------------------------
// Helpers
// ---------------------------------------------------------------------------
__device__ __forceinline__ unsigned f2tf(float f) {
    unsigned u;
    asm("cvt.rna.tf32.f32 %0, %1;" : "=r"(u) : "f"(f));
    return u;
}

__device__ __forceinline__ void mma8(float c[4],
                                     unsigned a0, unsigned a1, unsigned a2, unsigned a3,
                                     unsigned b0, unsigned b1) {
    asm volatile(
        "mma.sync.aligned.m16n8k8.row.col.f32.tf32.tf32.f32 "
        "{%0,%1,%2,%3}, {%4,%5,%6,%7}, {%8,%9}, {%0,%1,%2,%3};\n"
        : "+f"(c[0]), "+f"(c[1]), "+f"(c[2]), "+f"(c[3])
        : "r"(a0), "r"(a1), "r"(a2), "r"(a3), "r"(b0), "r"(b1));
}

// ---------------------------------------------------------------------------
// Projection: Y[M,64] = X[M,512] @ W[512,64] + b, split-tf32 (3-term) for
// near-fp32 accuracy. Block = 128 threads (4 warps), 64x64 output tile.
// ---------------------------------------------------------------------------
#define XS 68   // A-operand smem stride (bank-conflict-free for A-frag loads)
#define WS 72   // B-operand smem stride (bank-conflict-free for B-frag loads)

__global__ __launch_bounds__(128) void proj_mma(
    const float* __restrict__ X, const float* __restrict__ W,
    const float* __restrict__ bias, float* __restrict__ Y)
{
    extern __shared__ unsigned psm[];
    unsigned* Xh = psm;               // [64][XS]
    unsigned* Xl = Xh + 64 * XS;
    unsigned* Wh = Xl + 64 * XS;      // [64][WS]
    unsigned* Wl = Wh + 64 * WS;

    const int tid  = threadIdx.x;
    const int warp = tid >> 5;
    const int lane = tid & 31;
    const int gid  = lane >> 2;   // 0..7
    const int tg   = lane & 3;    // 0..3
    const int r0   = blockIdx.x * 64;

    float acc[8][4];
#pragma unroll
    for (int n = 0; n < 8; n++)
#pragma unroll
        for (int j = 0; j < 4; j++) acc[n][j] = 0.0f;

    for (int kc = 0; kc < DIN; kc += 64) {
        // Load X tile (64x64) -> hi/lo tf32 planes
        for (int v = tid; v < 1024; v += 128) {
            int row = v >> 4, c4 = (v & 15) * 4;
            float4 x = *(const float4*)&X[(size_t)(r0 + row) * DIN + kc + c4];
            unsigned h0 = f2tf(x.x), h1 = f2tf(x.y), h2 = f2tf(x.z), h3 = f2tf(x.w);
            *(uint4*)&Xh[row * XS + c4] = make_uint4(h0, h1, h2, h3);
            *(uint4*)&Xl[row * XS + c4] = make_uint4(
                f2tf(x.x - __uint_as_float(h0)), f2tf(x.y - __uint_as_float(h1)),
                f2tf(x.z - __uint_as_float(h2)), f2tf(x.w - __uint_as_float(h3)));
        }
        // Load W tile (64x64) -> hi/lo planes
        for (int v = tid; v < 1024; v += 128) {
            int row = v >> 4, c4 = (v & 15) * 4;
            float4 w = *(const float4*)&W[(size_t)(kc + row) * DK + c4];
            unsigned h0 = f2tf(w.x), h1 = f2tf(w.y), h2 = f2tf(w.z), h3 = f2tf(w.w);
            *(uint4*)&Wh[row * WS + c4] = make_uint4(h0, h1, h2, h3);
            *(uint4*)&Wl[row * WS + c4] = make_uint4(
                f2tf(w.x - __uint_as_float(h0)), f2tf(w.y - __uint_as_float(h1)),
                f2tf(w.z - __uint_as_float(h2)), f2tf(w.w - __uint_as_float(h3)));
        }
        __syncthreads();

#pragma unroll
        for (int ks = 0; ks < 8; ks++) {
            const int arow = warp * 16 + gid;
            const int acol = ks * 8 + tg;
            unsigned ah0 = Xh[arow * XS + acol];
            unsigned ah1 = Xh[(arow + 8) * XS + acol];
            unsigned ah2 = Xh[arow * XS + acol + 4];
            unsigned ah3 = Xh[(arow + 8) * XS + acol + 4];
            unsigned al0 = Xl[arow * XS + acol];
            unsigned al1 = Xl[(arow + 8) * XS + acol];
            unsigned al2 = Xl[arow * XS + acol + 4];
            unsigned al3 = Xl[(arow + 8) * XS + acol + 4];
#pragma unroll
            for (int nt = 0; nt < 8; nt++) {
                const int bk = ks * 8 + tg;
                const int bn = nt * 8 + gid;
                unsigned bh0 = Wh[bk * WS + bn];
                unsigned bh1 = Wh[(bk + 4) * WS + bn];
                unsigned bl0 = Wl[bk * WS + bn];
                unsigned bl1 = Wl[(bk + 4) * WS + bn];
                mma8(acc[nt], ah0, ah1, ah2, ah3, bh0, bh1);
                mma8(acc[nt], ah0, ah1, ah2, ah3, bl0, bl1);
                mma8(acc[nt], al0, al1, al2, al3, bh0, bh1);
            }
        }
        __syncthreads();
    }

    const int row = r0 + warp * 16 + gid;
#pragma unroll
    for (int nt = 0; nt < 8; nt++) {
        const int col = nt * 8 + tg * 2;
        float b0 = bias[col], b1 = bias[col + 1];
        *(float2*)&Y[(size_t)row * DK + col] =
            make_float2(acc[nt][0] + b0, acc[nt][1] + b1);
        *(float2*)&Y[(size_t)(row + 8) * DK + col] =
            make_float2(acc[nt][2] + b0, acc[nt][3] + b1);
    }
}

// ---------------------------------------------------------------------------
// Flash attention with tf32 MMA. Block = 128 threads (4 warps), 64-row Q tile,
// 64-key KV tiles. Q fragments live in registers for the whole pass; P is
// converted C-frag -> A-frag via quad shuffles (no smem round trip).
// ---------------------------------------------------------------------------
#define KSTR 72   // K/V smem stride (conflict-free for both B-frag patterns)

__global__ __launch_bounds__(128) void attn_mma(float* __restrict__ out)
{
    __shared__ unsigned Ks[64 * KSTR];
    __shared__ unsigned Vs[64 * KSTR];

    const int tid  = threadIdx.x;
    const int warp = tid >> 5;
    const int lane = tid & 31;
    const int gid  = lane >> 2;
    const int tg   = lane & 3;
    const int b    = blockIdx.y;
    const int qt   = blockIdx.x;
    const unsigned FULL = 0xffffffffu;

    // Load Q fragments (scale folded before tf32 conversion; 0.125 is exact)
    const float scale = 0.125f;
    const size_t qoff = ((size_t)b * SEQ + qt * 64 + warp * 16) * DK;
    unsigned aq[8][4];
#pragma unroll
    for (int ks = 0; ks < 8; ks++) {
        const int c = ks * 8 + tg;
        aq[ks][0] = f2tf(g_q[qoff + (size_t)gid * DK + c] * scale);
        aq[ks][1] = f2tf(g_q[qoff + (size_t)(gid + 8) * DK + c] * scale);
        aq[ks][2] = f2tf(g_q[qoff + (size_t)gid * DK + c + 4] * scale);
        aq[ks][3] = f2tf(g_q[qoff + (size_t)(gid + 8) * DK + c + 4] * scale);
    }

    float o[8][4];
#pragma unroll
    for (int n = 0; n < 8; n++)
#pragma unroll
        for (int j = 0; j < 4; j++) o[n][j] = 0.0f;
    float m0 = -1e30f, m1 = -1e30f, l0 = 0.0f, l1 = 0.0f;

    const int src0 = (lane & ~3) | (tg >> 1);
    const int src2 = src0 + 2;
    const bool odd = tg & 1;

    for (int kt = 0; kt < SEQ / 64; kt++) {
        __syncthreads();   // previous tile's readers done
        const size_t kb = ((size_t)b * SEQ + kt * 64) * DK;
        for (int v = tid; v < 1024; v += 128) {
            int row = v >> 4, c4 = (v & 15) * 4;
            float4 x = *(const float4*)&g_k[kb + (size_t)row * DK + c4];
            *(uint4*)&Ks[row * KSTR + c4] =
                make_uint4(f2tf(x.x), f2tf(x.y), f2tf(x.z), f2tf(x.w));
            float4 y = *(const float4*)&g_v[kb + (size_t)row * DK + c4];
            *(uint4*)&Vs[row * KSTR + c4] =
                make_uint4(f2tf(y.x), f2tf(y.y), f2tf(y.z), f2tf(y.w));
        }
        __syncthreads();

        // S = Q @ K^T (scale pre-folded)
        float s[8][4];
#pragma unroll
        for (int n = 0; n < 8; n++)
#pragma unroll
            for (int j = 0; j < 4; j++) s[n][j] = 0.0f;
#pragma unroll
        for (int ks = 0; ks < 8; ks++) {
#pragma unroll
            for (int nt = 0; nt < 8; nt++) {
                unsigned b0 = Ks[(nt * 8 + gid) * KSTR + ks * 8 + tg];
                unsigned b1 = Ks[(nt * 8 + gid) * KSTR + ks * 8 + tg + 4];
                mma8(s[nt], aq[ks][0], aq[ks][1], aq[ks][2], aq[ks][3], b0, b1);
            }
        }

        // Online softmax: row r=gid (c0,c1) and r+8 (c2,c3); quad = same row.
        float rm0 = -1e30f, rm1 = -1e30f;
#pragma unroll
        for (int n = 0; n < 8; n++) {
            rm0 = fmaxf(rm0, fmaxf(s[n][0], s[n][1]));
            rm1 = fmaxf(rm1, fmaxf(s[n][2], s[n][3]));
        }
        rm0 = fmaxf(rm0, __shfl_xor_sync(FULL, rm0, 1));
        rm0 = fmaxf(rm0, __shfl_xor_sync(FULL, rm0, 2));
        rm1 = fmaxf(rm1, __shfl_xor_sync(FULL, rm1, 1));
        rm1 = fmaxf(rm1, __shfl_xor_sync(FULL, rm1, 2));
        const float mn0 = fmaxf(m0, rm0);
        const float mn1 = fmaxf(m1, rm1);
        float rs0 = 0.0f, rs1 = 0.0f;
#pragma unroll
        for (int n = 0; n < 8; n++) {
            s[n][0] = __expf(s[n][0] - mn0);
            s[n][1] = __expf(s[n][1] - mn0);
            s[n][2] = __expf(s[n][2] - mn1);
            s[n][3] = __expf(s[n][3] - mn1);
            rs0 += s[n][0] + s[n][1];
            rs1 += s[n][2] + s[n][3];
        }
        rs0 += __shfl_xor_sync(FULL, rs0, 1);
        rs0 += __shfl_xor_sync(FULL, rs0, 2);
        rs1 += __shfl_xor_sync(FULL, rs1, 1);
        rs1 += __shfl_xor_sync(FULL, rs1, 2);
        const float al0 = __expf(m0 - mn0);
        const float al1 = __expf(m1 - mn1);
        l0 = l0 * al0 + rs0;
        l1 = l1 * al1 + rs1;
        m0 = mn0;
        m1 = mn1;
#pragma unroll
        for (int n = 0; n < 8; n++) {
            o[n][0] *= al0; o[n][1] *= al0;
            o[n][2] *= al1; o[n][3] *= al1;
        }

        // O += P @ V ; P C-frag -> A-frag via quad shuffles
#pragma unroll
        for (int j = 0; j < 8; j++) {
            float x0 = __shfl_sync(FULL, s[j][0], src0);
            float x1 = __shfl_sync(FULL, s[j][1], src0);
            float y0 = __shfl_sync(FULL, s[j][0], src2);
            float y1 = __shfl_sync(FULL, s[j][1], src2);
            float z0 = __shfl_sync(FULL, s[j][2], src0);
            float z1 = __shfl_sync(FULL, s[j][3], src0);
            float w0 = __shfl_sync(FULL, s[j][2], src2);
            float w1 = __shfl_sync(FULL, s[j][3], src2);
            unsigned pa0 = f2tf(odd ? x1 : x0);   // (row,   k=tg)
            unsigned pa1 = f2tf(odd ? z1 : z0);   // (row+8, k=tg)
            unsigned pa2 = f2tf(odd ? y1 : y0);   // (row,   k=tg+4)
            unsigned pa3 = f2tf(odd ? w1 : w0);   // (row+8, k=tg+4)
#pragma unroll
            for (int nt = 0; nt < 8; nt++) {
                unsigned b0 = Vs[(j * 8 + tg) * KSTR + nt * 8 + gid];
                unsigned b1 = Vs[(j * 8 + tg + 4) * KSTR + nt * 8 + gid];
                mma8(o[nt], pa0, pa1, pa2, pa3, b0, b1);
            }
        }
    }

    // Epilogue: normalize and store
    const size_t obase = ((size_t)b * SEQ + qt * 64 + warp * 16) * DK;
    const float inv0 = 1.0f / l0;
    const float inv1 = 1.0f / l1;
#pragma unroll
    for (int nt = 0; nt < 8; nt++) {
        const int col = nt * 8 + tg * 2;
        *(float2*)&out[obase + (size_t)gid * DK + col] =
            make_float2(o[nt][0] * inv0, o[nt][1] * inv0);
        *(float2*)&out[obase + (size_t)(gid + 8) * DK + col] =
            make_float2(o[nt][2] * inv1, o[nt][3] * inv1);
    }
}

// ---------------------------------------------------------------------------
extern "C" void kernel_launch(void* const* d_in, const int* in_sizes, int n_in,
                              void* d_out, int out_size)
{
    const float* q_in = (const float*)d_in[0];
    const float* k_in = (const float*)d_in[1];
    const float* v_in = (const float*)d_in[2];
    const float* Wq   = (const float*)d_in[3];
    const float* bq   = (const float*)d_in[4];
    const float* Wk   = (const float*)d_in[5];
    const float* bk   = (const float*)d_in[6];
    const float* Wv   = (const float*)d_in[7];
    const float* bv   = (const float*)d_in[8];
    float* out = (float*)d_out;

    float *qp, *kp, *vp;
    cudaGetSymbolAddress((void**)&qp, g_q);
    cudaGetSymbolAddress((void**)&kp, g_k);
    cudaGetSymbolAddress((void**)&vp, g_v);

    const int proj_smem = (2 * 64 * XS + 2 * 64 * WS) * (int)sizeof(unsigned); // 71,680
    static int smem_set = 0;
    if (!smem_set) {
        cudaFuncSetAttribute(proj_mma,
                             cudaFuncAttributeMaxDynamicSharedMemorySize,
                             proj_smem);
        smem_set = 1;
    }

    proj_mma<<<MTOT / 64, 128, proj_smem>>>(q_in, Wq, bq, qp);
    proj_mma<<<MTOT / 64, 128, proj_smem>>>(k_in, Wk, bk, kp);
    proj_mma<<<MTOT / 64, 128, proj_smem>>>(v_in, Wv, bv, vp);

    dim3 agrid(SEQ / 64, NB);
    attn_mma<<<agrid, 128>>>(out);
}

// round 10
// speedup vs baseline: 2.2244x; 1.0524x over previous
#include <cuda_runtime.h>

#define NB  8
#define SEQ 2048
#define DIN 512
#define DK  64
#define MTOT (NB*SEQ)   // 16384
#define SPLIT 4         // flash split-K factor

// Scratch — __device__ globals, no allocation.
__device__ float g_q[MTOT * DK];
__device__ float g_k[MTOT * DK];
__device__ float g_v[MTOT * DK];
__device__ float g_op[SPLIT * MTOT * DK];   // unnormalized partial O (16.8 MB)
__device__ float g_ms[SPLIT * MTOT];        // per-split row max
__device__ float g_ls[SPLIT * MTOT];        // per-split row sum

// ---------------------------------------------------------------------------
// Helpers
// ---------------------------------------------------------------------------
__device__ __forceinline__ unsigned f2tf(float f) {
    unsigned u;
    asm("cvt.rna.tf32.f32 %0, %1;" : "=r"(u) : "f"(f));
    return u;
}

__device__ __forceinline__ void mma8(float c[4],
                                     unsigned a0, unsigned a1, unsigned a2, unsigned a3,
                                     unsigned b0, unsigned b1) {
    asm volatile(
        "mma.sync.aligned.m16n8k8.row.col.f32.tf32.tf32.f32 "
        "{%0,%1,%2,%3}, {%4,%5,%6,%7}, {%8,%9}, {%0,%1,%2,%3};\n"
        : "+f"(c[0]), "+f"(c[1]), "+f"(c[2]), "+f"(c[3])
        : "r"(a0), "r"(a1), "r"(a2), "r"(a3), "r"(b0), "r"(b1));
}

// ---------------------------------------------------------------------------
// Fused projection: blockIdx.y selects (q|k|v). Y[M,64] = X[M,512] @ W + b.
// 2-term split-tf32: X split into hi/lo planes, W single tf32 plane.
// Block = 128 threads (4 warps), 64x64 output tile. Grid = (256, 3).
// ---------------------------------------------------------------------------
#define XS 68   // A-operand smem stride (conflict-free)
#define WS 72   // B-operand smem stride (conflict-free)

__global__ __launch_bounds__(128) void proj_mma(
    const float* __restrict__ Xq, const float* __restrict__ Xk, const float* __restrict__ Xv,
    const float* __restrict__ Wq, const float* __restrict__ Wk, const float* __restrict__ Wv,
    const float* __restrict__ bq, const float* __restrict__ bk, const float* __restrict__ bv,
    float* __restrict__ Yq, float* __restrict__ Yk, float* __restrict__ Yv)
{
    extern __shared__ unsigned psm[];
    unsigned* Xh  = psm;               // [64][XS]
    unsigned* Xl  = Xh + 64 * XS;
    unsigned* Wsm = Xl + 64 * XS;      // [64][WS]

    const int which = blockIdx.y;
    const float* X    = which == 0 ? Xq : which == 1 ? Xk : Xv;
    const float* W    = which == 0 ? Wq : which == 1 ? Wk : Wv;
    const float* bias = which == 0 ? bq : which == 1 ? bk : bv;
    float*       Y    = which == 0 ? Yq : which == 1 ? Yk : Yv;

    const int tid  = threadIdx.x;
    const int warp = tid >> 5;
    const int lane = tid & 31;
    const int gid  = lane >> 2;   // 0..7
    const int tg   = lane & 3;    // 0..3
    const int r0   = blockIdx.x * 64;

    float acc[8][4];
#pragma unroll
    for (int n = 0; n < 8; n++)
#pragma unroll
        for (int j = 0; j < 4; j++) acc[n][j] = 0.0f;

    for (int kc = 0; kc < DIN; kc += 64) {
        // X tile (64x64) -> hi/lo tf32 planes
        for (int v = tid; v < 1024; v += 128) {
            int row = v >> 4, c4 = (v & 15) * 4;
            float4 x = *(const float4*)&X[(size_t)(r0 + row) * DIN + kc + c4];
            unsigned h0 = f2tf(x.x), h1 = f2tf(x.y), h2 = f2tf(x.z), h3 = f2tf(x.w);
            *(uint4*)&Xh[row * XS + c4] = make_uint4(h0, h1, h2, h3);
            *(uint4*)&Xl[row * XS + c4] = make_uint4(
                f2tf(x.x - __uint_as_float(h0)), f2tf(x.y - __uint_as_float(h1)),
                f2tf(x.z - __uint_as_float(h2)), f2tf(x.w - __uint_as_float(h3)));
        }
        // W tile (64x64) -> single tf32 plane
        for (int v = tid; v < 1024; v += 128) {
            int row = v >> 4, c4 = (v & 15) * 4;
            float4 w = *(const float4*)&W[(size_t)(kc + row) * DK + c4];
            *(uint4*)&Wsm[row * WS + c4] =
                make_uint4(f2tf(w.x), f2tf(w.y), f2tf(w.z), f2tf(w.w));
        }
        __syncthreads();

#pragma unroll
        for (int ks = 0; ks < 8; ks++) {
            const int arow = warp * 16 + gid;
            const int acol = ks * 8 + tg;
            unsigned ah0 = Xh[arow * XS + acol];
            unsigned ah1 = Xh[(arow + 8) * XS + acol];
            unsigned ah2 = Xh[arow * XS + acol + 4];
            unsigned ah3 = Xh[(arow + 8) * XS + acol + 4];
            unsigned al0 = Xl[arow * XS + acol];
            unsigned al1 = Xl[(arow + 8) * XS + acol];
            unsigned al2 = Xl[arow * XS + acol + 4];
            unsigned al3 = Xl[(arow + 8) * XS + acol + 4];
#pragma unroll
            for (int nt = 0; nt < 8; nt++) {
                const int bk = ks * 8 + tg;
                const int bn = nt * 8 + gid;
                unsigned bh0 = Wsm[bk * WS + bn];
                unsigned bh1 = Wsm[(bk + 4) * WS + bn];
                mma8(acc[nt], ah0, ah1, ah2, ah3, bh0, bh1);
                mma8(acc[nt], al0, al1, al2, al3, bh0, bh1);
            }
        }
        __syncthreads();
    }

    const int row = r0 + warp * 16 + gid;
#pragma unroll
    for (int nt = 0; nt < 8; nt++) {
        const int col = nt * 8 + tg * 2;
        float b0 = bias[col], b1 = bias[col + 1];
        *(float2*)&Y[(size_t)row * DK + col] =
            make_float2(acc[nt][0] + b0, acc[nt][1] + b1);
        *(float2*)&Y[(size_t)(row + 8) * DK + col] =
            make_float2(acc[nt][2] + b0, acc[nt][3] + b1);
    }
}

// ---------------------------------------------------------------------------
// Flash attention, split-K x SPLIT. Block = 128 threads (4 warps), 64-row Q
// tile; blockIdx.z selects a 512-key slice (8 KV tiles). Writes unnormalized
// partial O plus per-row (m, l); combine kernel merges the splits.
// ---------------------------------------------------------------------------
#define KSTR 72

__global__ __launch_bounds__(128) void attn_mma()
{
    __shared__ unsigned Ks[64 * KSTR];
    __shared__ unsigned Vs[64 * KSTR];

    const int tid  = threadIdx.x;
    const int warp = tid >> 5;
    const int lane = tid & 31;
    const int gid  = lane >> 2;
    const int tg   = lane & 3;
    const int b    = blockIdx.y;
    const int qt   = blockIdx.x;
    const int sp   = blockIdx.z;
    const unsigned FULL = 0xffffffffu;

    const float scale = 0.125f;
    const size_t qoff = ((size_t)b * SEQ + qt * 64 + warp * 16) * DK;
    unsigned aq[8][4];
#pragma unroll
    for (int ks = 0; ks < 8; ks++) {
        const int c = ks * 8 + tg;
        aq[ks][0] = f2tf(g_q[qoff + (size_t)gid * DK + c] * scale);
        aq[ks][1] = f2tf(g_q[qoff + (size_t)(gid + 8) * DK + c] * scale);
        aq[ks][2] = f2tf(g_q[qoff + (size_t)gid * DK + c + 4] * scale);
        aq[ks][3] = f2tf(g_q[qoff + (size_t)(gid + 8) * DK + c + 4] * scale);
    }

    float o[8][4];
#pragma unroll
    for (int n = 0; n < 8; n++)
#pragma unroll
        for (int j = 0; j < 4; j++) o[n][j] = 0.0f;
    float m0 = -1e30f, m1 = -1e30f, l0 = 0.0f, l1 = 0.0f;

    const int src0 = (lane & ~3) | (tg >> 1);
    const int src2 = src0 + 2;
    const bool odd = tg & 1;

    const int kt0 = sp * (SEQ / 64 / SPLIT);
    const int kt1 = kt0 + SEQ / 64 / SPLIT;
    for (int kt = kt0; kt < kt1; kt++) {
        __syncthreads();
        const size_t kb = ((size_t)b * SEQ + kt * 64) * DK;
        for (int v = tid; v < 1024; v += 128) {
            int row = v >> 4, c4 = (v & 15) * 4;
            float4 x = *(const float4*)&g_k[kb + (size_t)row * DK + c4];
            *(uint4*)&Ks[row * KSTR + c4] =
                make_uint4(f2tf(x.x), f2tf(x.y), f2tf(x.z), f2tf(x.w));
            float4 y = *(const float4*)&g_v[kb + (size_t)row * DK + c4];
            *(uint4*)&Vs[row * KSTR + c4] =
                make_uint4(f2tf(y.x), f2tf(y.y), f2tf(y.z), f2tf(y.w));
        }
        __syncthreads();

        // S = Q @ K^T
        float s[8][4];
#pragma unroll
        for (int n = 0; n < 8; n++)
#pragma unroll
            for (int j = 0; j < 4; j++) s[n][j] = 0.0f;
#pragma unroll
        for (int ks = 0; ks < 8; ks++) {
#pragma unroll
            for (int nt = 0; nt < 8; nt++) {
                unsigned b0 = Ks[(nt * 8 + gid) * KSTR + ks * 8 + tg];
                unsigned b1 = Ks[(nt * 8 + gid) * KSTR + ks * 8 + tg + 4];
                mma8(s[nt], aq[ks][0], aq[ks][1], aq[ks][2], aq[ks][3], b0, b1);
            }
        }

        // Online softmax
        float rm0 = -1e30f, rm1 = -1e30f;
#pragma unroll
        for (int n = 0; n < 8; n++) {
            rm0 = fmaxf(rm0, fmaxf(s[n][0], s[n][1]));
            rm1 = fmaxf(rm1, fmaxf(s[n][2], s[n][3]));
        }
        rm0 = fmaxf(rm0, __shfl_xor_sync(FULL, rm0, 1));
        rm0 = fmaxf(rm0, __shfl_xor_sync(FULL, rm0, 2));
        rm1 = fmaxf(rm1, __shfl_xor_sync(FULL, rm1, 1));
        rm1 = fmaxf(rm1, __shfl_xor_sync(FULL, rm1, 2));
        const float mn0 = fmaxf(m0, rm0);
        const float mn1 = fmaxf(m1, rm1);
        float rs0 = 0.0f, rs1 = 0.0f;
#pragma unroll
        for (int n = 0; n < 8; n++) {
            s[n][0] = __expf(s[n][0] - mn0);
            s[n][1] = __expf(s[n][1] - mn0);
            s[n][2] = __expf(s[n][2] - mn1);
            s[n][3] = __expf(s[n][3] - mn1);
            rs0 += s[n][0] + s[n][1];
            rs1 += s[n][2] + s[n][3];
        }
        rs0 += __shfl_xor_sync(FULL, rs0, 1);
        rs0 += __shfl_xor_sync(FULL, rs0, 2);
        rs1 += __shfl_xor_sync(FULL, rs1, 1);
        rs1 += __shfl_xor_sync(FULL, rs1, 2);
        const float al0 = __expf(m0 - mn0);
        const float al1 = __expf(m1 - mn1);
        l0 = l0 * al0 + rs0;
        l1 = l1 * al1 + rs1;
        m0 = mn0;
        m1 = mn1;
#pragma unroll
        for (int n = 0; n < 8; n++) {
            o[n][0] *= al0; o[n][1] *= al0;
            o[n][2] *= al1; o[n][3] *= al1;
        }

        // O += P @ V ; C-frag -> A-frag via quad shuffles
#pragma unroll
        for (int j = 0; j < 8; j++) {
            float x0 = __shfl_sync(FULL, s[j][0], src0);
            float x1 = __shfl_sync(FULL, s[j][1], src0);
            float y0 = __shfl_sync(FULL, s[j][0], src2);
            float y1 = __shfl_sync(FULL, s[j][1], src2);
            float z0 = __shfl_sync(FULL, s[j][2], src0);
            float z1 = __shfl_sync(FULL, s[j][3], src0);
            float w0 = __shfl_sync(FULL, s[j][2], src2);
            float w1 = __shfl_sync(FULL, s[j][3], src2);
            unsigned pa0 = f2tf(odd ? x1 : x0);
            unsigned pa1 = f2tf(odd ? z1 : z0);
            unsigned pa2 = f2tf(odd ? y1 : y0);
            unsigned pa3 = f2tf(odd ? w1 : w0);
#pragma unroll
            for (int nt = 0; nt < 8; nt++) {
                unsigned b0 = Vs[(j * 8 + tg) * KSTR + nt * 8 + gid];
                unsigned b1 = Vs[(j * 8 + tg + 4) * KSTR + nt * 8 + gid];
                mma8(o[nt], pa0, pa1, pa2, pa3, b0, b1);
            }
        }
    }

    // Epilogue: store UNNORMALIZED partial O + per-row (m, l)
    const int rowb = b * SEQ + qt * 64 + warp * 16;
    const size_t obase = ((size_t)sp * MTOT + rowb) * DK;
#pragma unroll
    for (int nt = 0; nt < 8; nt++) {
        const int col = nt * 8 + tg * 2;
        *(float2*)&g_op[obase + (size_t)gid * DK + col] =
            make_float2(o[nt][0], o[nt][1]);
        *(float2*)&g_op[obase + (size_t)(gid + 8) * DK + col] =
            make_float2(o[nt][2], o[nt][3]);
    }
    if (tg == 0) {
        g_ms[sp * MTOT + rowb + gid]     = m0;
        g_ls[sp * MTOT + rowb + gid]     = l0;
        g_ms[sp * MTOT + rowb + gid + 8] = m1;
        g_ls[sp * MTOT + rowb + gid + 8] = l1;
    }
}

// ---------------------------------------------------------------------------
// Combine the SPLIT partials: out = (sum_i o_i * exp(m_i - M)) / (sum_i l_i * exp(m_i - M))
// ---------------------------------------------------------------------------
__global__ __launch_bounds__(256) void combine_kernel(float* __restrict__ out)
{
    const int idx = blockIdx.x * 256 + threadIdx.x;   // over MTOT*DK
    const int row = idx >> 6;

    float mv[SPLIT];
    float M = -1e30f;
#pragma unroll
    for (int i = 0; i < SPLIT; i++) {
        mv[i] = g_ms[i * MTOT + row];
        M = fmaxf(M, mv[i]);
    }
    float L = 0.0f, acc = 0.0f;
#pragma unroll
    for (int i = 0; i < SPLIT; i++) {
        const float w = __expf(mv[i] - M);
        L   += g_ls[i * MTOT + row] * w;
        acc += g_op[(size_t)i * MTOT * DK + idx] * w;
    }
    out[idx] = acc / L;
}

// ---------------------------------------------------------------------------
extern "C" void kernel_launch(void* const* d_in, const int* in_sizes, int n_in,
                              void* d_out, int out_size)
{
    const float* q_in = (const float*)d_in[0];
    const float* k_in = (const float*)d_in[1];
    const float* v_in = (const float*)d_in[2];
    const float* Wq   = (const float*)d_in[3];
    const float* bq   = (const float*)d_in[4];
    const float* Wk   = (const float*)d_in[5];
    const float* bk   = (const float*)d_in[6];
    const float* Wv   = (const float*)d_in[7];
    const float* bv   = (const float*)d_in[8];
    float* out = (float*)d_out;

    float *qp, *kp, *vp;
    cudaGetSymbolAddress((void**)&qp, g_q);
    cudaGetSymbolAddress((void**)&kp, g_k);
    cudaGetSymbolAddress((void**)&vp, g_v);

    const int proj_smem = (2 * 64 * XS + 64 * WS) * (int)sizeof(unsigned); // 53,248
    static int smem_set = 0;
    if (!smem_set) {
        cudaFuncSetAttribute(proj_mma,
                             cudaFuncAttributeMaxDynamicSharedMemorySize,
                             proj_smem);
        smem_set = 1;
    }

    dim3 pgrid(MTOT / 64, 3);
    proj_mma<<<pgrid, 128, proj_smem>>>(q_in, k_in, v_in, Wq, Wk, Wv,
                                        bq, bk, bv, qp, kp, vp);

    dim3 agrid(SEQ / 64, NB, SPLIT);
    attn_mma<<<agrid, 128>>>();

    combine_kernel<<<MTOT * DK / 256, 256>>>(out);
}

// round 11
// speedup vs baseline: 3.2531x; 1.4625x over previous
#include <cuda_runtime.h>

#define NB  8
#define SEQ 2048
#define DIN 512
#define DK  64
#define MTOT (NB*SEQ)   // 16384
#define SPLIT 4         // flash split-K factor

// Scratch — __device__ globals, no allocation.
// Projected Q (pre-scaled), K, V stored as tf32 bit patterns.
__device__ unsigned g_qt[MTOT * DK];
__device__ unsigned g_kt[MTOT * DK];
__device__ unsigned g_vt[MTOT * DK];
__device__ unsigned g_wt[3 * DIN * DK];     // pre-converted tf32 weights
__device__ float g_op[SPLIT * MTOT * DK];   // unnormalized partial O
__device__ float g_ms[SPLIT * MTOT];        // per-split row max
__device__ float g_ls[SPLIT * MTOT];        // per-split row sum

// ---------------------------------------------------------------------------
// Helpers
// ---------------------------------------------------------------------------
__device__ __forceinline__ unsigned f2tf(float f) {
    unsigned u;
    asm("cvt.rna.tf32.f32 %0, %1;" : "=r"(u) : "f"(f));
    return u;
}

__device__ __forceinline__ void mma8(float c[4],
                                     unsigned a0, unsigned a1, unsigned a2, unsigned a3,
                                     unsigned b0, unsigned b1) {
    asm volatile(
        "mma.sync.aligned.m16n8k8.row.col.f32.tf32.tf32.f32 "
        "{%0,%1,%2,%3}, {%4,%5,%6,%7}, {%8,%9}, {%0,%1,%2,%3};\n"
        : "+f"(c[0]), "+f"(c[1]), "+f"(c[2]), "+f"(c[3])
        : "r"(a0), "r"(a1), "r"(a2), "r"(a3), "r"(b0), "r"(b1));
}

__device__ __forceinline__ void cp16(const void* s, const void* g) {
    unsigned a = (unsigned)__cvta_generic_to_shared(s);
    asm volatile("cp.async.ca.shared.global [%0], [%1], 16;\n" :: "r"(a), "l"(g));
}
#define CP_COMMIT() asm volatile("cp.async.commit_group;\n" ::: "memory")
#define CP_WAIT1()  asm volatile("cp.async.wait_group 1;\n" ::: "memory")

// ---------------------------------------------------------------------------
// One-time weight conversion: W[512,64] x3 -> tf32 bit patterns.
// ---------------------------------------------------------------------------
__global__ __launch_bounds__(256) void convert_w(
    const float* __restrict__ Wq, const float* __restrict__ Wk,
    const float* __restrict__ Wv)
{
    const int v = blockIdx.x * 256 + threadIdx.x;   // float4 index: 3*8192 total
    const int which = v >> 13;
    const int off = (v & 8191) * 4;
    const float* W = which == 0 ? Wq : which == 1 ? Wk : Wv;
    float4 w = *(const float4*)&W[off];
    *(uint4*)&g_wt[which * DIN * DK + off] =
        make_uint4(f2tf(w.x), f2tf(w.y), f2tf(w.z), f2tf(w.w));
}

// ---------------------------------------------------------------------------
// Fused projection, cp.async double-buffered. blockIdx.y selects (q|k|v).
// Block = 256 threads (8 warps), 128x64 output tile. 2-term split-tf32:
// X hi/lo split computed in the A-fragment build from raw fp32 smem.
// Epilogue writes tf32 bits (Q pre-scaled by 1/8).
// ---------------------------------------------------------------------------
#define XSP 68   // X smem stride (floats), conflict-free A-frag pattern
#define WSP 72   // W smem stride (uints), conflict-free B-frag pattern

__global__ __launch_bounds__(256) void proj_mma(
    const float* __restrict__ Xq, const float* __restrict__ Xk, const float* __restrict__ Xv,
    const float* __restrict__ bq, const float* __restrict__ bk, const float* __restrict__ bv)
{
    extern __shared__ float psm[];
    float*    Xs = psm;                              // [2][128*XSP]
    unsigned* Ws = (unsigned*)(psm + 2 * 128 * XSP); // [2][64*WSP]

    const int which = blockIdx.y;
    const float* X    = which == 0 ? Xq : which == 1 ? Xk : Xv;
    const float* bias = which == 0 ? bq : which == 1 ? bk : bv;
    unsigned*    Y    = which == 0 ? g_qt : which == 1 ? g_kt : g_vt;
    const float oscale = which == 0 ? 0.125f : 1.0f;
    const unsigned* Wg = &g_wt[which * DIN * DK];

    const int tid  = threadIdx.x;
    const int warp = tid >> 5;
    const int lane = tid & 31;
    const int gid  = lane >> 2;
    const int tg   = lane & 3;
    const int r0   = blockIdx.x * 128;

    auto stage = [&](int buf, int kc) {
        float* Xb = Xs + buf * 128 * XSP;
        unsigned* Wb = Ws + buf * 64 * WSP;
#pragma unroll
        for (int v = tid; v < 2048; v += 256) {   // X: 128x64 fp32 = 2048 f4
            int row = v >> 4, c4 = (v & 15) * 4;
            cp16(&Xb[row * XSP + c4], &X[(size_t)(r0 + row) * DIN + kc + c4]);
        }
#pragma unroll
        for (int v = tid; v < 1024; v += 256) {   // W: 64x64 tf32 = 1024 u4
            int row = v >> 4, c4 = (v & 15) * 4;
            cp16(&Wb[row * WSP + c4], &Wg[(kc + row) * DK + c4]);
        }
    };

    float acc[8][4];
#pragma unroll
    for (int n = 0; n < 8; n++)
#pragma unroll
        for (int j = 0; j < 4; j++) acc[n][j] = 0.0f;

    stage(0, 0);
    CP_COMMIT();

    for (int c = 0; c < 8; c++) {
        const int buf = c & 1;
        if (c < 7) stage(buf ^ 1, (c + 1) * 64);
        CP_COMMIT();
        CP_WAIT1();
        __syncthreads();

        const float* Xb = Xs + buf * 128 * XSP;
        const unsigned* Wb = Ws + buf * 64 * WSP;
#pragma unroll
        for (int ks = 0; ks < 8; ks++) {
            const int arow = warp * 16 + gid;
            const int acol = ks * 8 + tg;
            float f0 = Xb[arow * XSP + acol];
            float f1 = Xb[(arow + 8) * XSP + acol];
            float f2 = Xb[arow * XSP + acol + 4];
            float f3 = Xb[(arow + 8) * XSP + acol + 4];
            unsigned ah0 = f2tf(f0), ah1 = f2tf(f1), ah2 = f2tf(f2), ah3 = f2tf(f3);
            unsigned al0 = f2tf(f0 - __uint_as_float(ah0));
            unsigned al1 = f2tf(f1 - __uint_as_float(ah1));
            unsigned al2 = f2tf(f2 - __uint_as_float(ah2));
            unsigned al3 = f2tf(f3 - __uint_as_float(ah3));
#pragma unroll
            for (int nt = 0; nt < 8; nt++) {
                unsigned b0 = Wb[(ks * 8 + tg) * WSP + nt * 8 + gid];
                unsigned b1 = Wb[(ks * 8 + tg + 4) * WSP + nt * 8 + gid];
                mma8(acc[nt], ah0, ah1, ah2, ah3, b0, b1);
                mma8(acc[nt], al0, al1, al2, al3, b0, b1);
            }
        }
        __syncthreads();
    }

    const int row = r0 + warp * 16 + gid;
#pragma unroll
    for (int nt = 0; nt < 8; nt++) {
        const int col = nt * 8 + tg * 2;
        float b0 = bias[col], b1 = bias[col + 1];
        *(uint2*)&Y[(size_t)row * DK + col] = make_uint2(
            f2tf((acc[nt][0] + b0) * oscale), f2tf((acc[nt][1] + b1) * oscale));
        *(uint2*)&Y[(size_t)(row + 8) * DK + col] = make_uint2(
            f2tf((acc[nt][2] + b0) * oscale), f2tf((acc[nt][3] + b1) * oscale));
    }
}

// ---------------------------------------------------------------------------
// Flash attention, split-K x SPLIT, cp.async double-buffered K/V tiles.
// All operands are pre-converted tf32 bits: no conversion in the hot loop.
// Block = 128 threads (4 warps), 64-row Q tile, 64-key KV tiles.
// ---------------------------------------------------------------------------
#define KSTR 72

__global__ __launch_bounds__(128) void attn_mma()
{
    extern __shared__ unsigned asmem[];
    unsigned* Ks = asmem;                 // [2][64*KSTR]
    unsigned* Vs = asmem + 2 * 64 * KSTR; // [2][64*KSTR]

    const int tid  = threadIdx.x;
    const int warp = tid >> 5;
    const int lane = tid & 31;
    const int gid  = lane >> 2;
    const int tg   = lane & 3;
    const int b    = blockIdx.y;
    const int qt   = blockIdx.x;
    const int sp   = blockIdx.z;
    const unsigned FULL = 0xffffffffu;

    // Q fragments: direct LDG of pre-scaled tf32 bits
    const size_t qoff = ((size_t)b * SEQ + qt * 64 + warp * 16) * DK;
    unsigned aq[8][4];
#pragma unroll
    for (int ks = 0; ks < 8; ks++) {
        const int c = ks * 8 + tg;
        aq[ks][0] = g_qt[qoff + (size_t)gid * DK + c];
        aq[ks][1] = g_qt[qoff + (size_t)(gid + 8) * DK + c];
        aq[ks][2] = g_qt[qoff + (size_t)gid * DK + c + 4];
        aq[ks][3] = g_qt[qoff + (size_t)(gid + 8) * DK + c + 4];
    }

    float o[8][4];
#pragma unroll
    for (int n = 0; n < 8; n++)
#pragma unroll
        for (int j = 0; j < 4; j++) o[n][j] = 0.0f;
    float m0 = -1e30f, m1 = -1e30f, l0 = 0.0f, l1 = 0.0f;

    const int src0 = (lane & ~3) | (tg >> 1);
    const int src2 = src0 + 2;
    const bool odd = tg & 1;
    const int kt0 = sp * (SEQ / 64 / SPLIT);

    auto stage = [&](int buf, int kt) {
        const size_t kb = ((size_t)b * SEQ + kt * 64) * DK;
        unsigned* Kb = Ks + buf * 64 * KSTR;
        unsigned* Vb = Vs + buf * 64 * KSTR;
#pragma unroll
        for (int v = tid; v < 1024; v += 128) {   // 64x64 u32 = 1024 u4 each
            int row = v >> 4, c4 = (v & 15) * 4;
            cp16(&Kb[row * KSTR + c4], &g_kt[kb + (size_t)row * DK + c4]);
            cp16(&Vb[row * KSTR + c4], &g_vt[kb + (size_t)row * DK + c4]);
        }
    };

    stage(0, kt0);
    CP_COMMIT();

    for (int c = 0; c < SEQ / 64 / SPLIT; c++) {
        const int buf = c & 1;
        if (c < SEQ / 64 / SPLIT - 1) stage(buf ^ 1, kt0 + c + 1);
        CP_COMMIT();
        CP_WAIT1();
        __syncthreads();

        const unsigned* Kb = Ks + buf * 64 * KSTR;
        const unsigned* Vb = Vs + buf * 64 * KSTR;

        // S = Q @ K^T
        float s[8][4];
#pragma unroll
        for (int n = 0; n < 8; n++)
#pragma unroll
            for (int j = 0; j < 4; j++) s[n][j] = 0.0f;
#pragma unroll
        for (int ks = 0; ks < 8; ks++) {
#pragma unroll
            for (int nt = 0; nt < 8; nt++) {
                unsigned b0 = Kb[(nt * 8 + gid) * KSTR + ks * 8 + tg];
                unsigned b1 = Kb[(nt * 8 + gid) * KSTR + ks * 8 + tg + 4];
                mma8(s[nt], aq[ks][0], aq[ks][1], aq[ks][2], aq[ks][3], b0, b1);
            }
        }

        // Online softmax
        float rm0 = -1e30f, rm1 = -1e30f;
#pragma unroll
        for (int n = 0; n < 8; n++) {
            rm0 = fmaxf(rm0, fmaxf(s[n][0], s[n][1]));
            rm1 = fmaxf(rm1, fmaxf(s[n][2], s[n][3]));
        }
        rm0 = fmaxf(rm0, __shfl_xor_sync(FULL, rm0, 1));
        rm0 = fmaxf(rm0, __shfl_xor_sync(FULL, rm0, 2));
        rm1 = fmaxf(rm1, __shfl_xor_sync(FULL, rm1, 1));
        rm1 = fmaxf(rm1, __shfl_xor_sync(FULL, rm1, 2));
        const float mn0 = fmaxf(m0, rm0);
        const float mn1 = fmaxf(m1, rm1);
        float rs0 = 0.0f, rs1 = 0.0f;
#pragma unroll
        for (int n = 0; n < 8; n++) {
            s[n][0] = __expf(s[n][0] - mn0);
            s[n][1] = __expf(s[n][1] - mn0);
            s[n][2] = __expf(s[n][2] - mn1);
            s[n][3] = __expf(s[n][3] - mn1);
            rs0 += s[n][0] + s[n][1];
            rs1 += s[n][2] + s[n][3];
        }
        rs0 += __shfl_xor_sync(FULL, rs0, 1);
        rs0 += __shfl_xor_sync(FULL, rs0, 2);
        rs1 += __shfl_xor_sync(FULL, rs1, 1);
        rs1 += __shfl_xor_sync(FULL, rs1, 2);
        const float al0 = __expf(m0 - mn0);
        const float al1 = __expf(m1 - mn1);
        l0 = l0 * al0 + rs0;
        l1 = l1 * al1 + rs1;
        m0 = mn0;
        m1 = mn1;
#pragma unroll
        for (int n = 0; n < 8; n++) {
            o[n][0] *= al0; o[n][1] *= al0;
            o[n][2] *= al1; o[n][3] *= al1;
        }

        // O += P @ V ; C-frag -> A-frag via quad shuffles
#pragma unroll
        for (int j = 0; j < 8; j++) {
            float x0 = __shfl_sync(FULL, s[j][0], src0);
            float x1 = __shfl_sync(FULL, s[j][1], src0);
            float y0 = __shfl_sync(FULL, s[j][0], src2);
            float y1 = __shfl_sync(FULL, s[j][1], src2);
            float z0 = __shfl_sync(FULL, s[j][2], src0);
            float z1 = __shfl_sync(FULL, s[j][3], src0);
            float w0 = __shfl_sync(FULL, s[j][2], src2);
            float w1 = __shfl_sync(FULL, s[j][3], src2);
            unsigned pa0 = f2tf(odd ? x1 : x0);
            unsigned pa1 = f2tf(odd ? z1 : z0);
            unsigned pa2 = f2tf(odd ? y1 : y0);
            unsigned pa3 = f2tf(odd ? w1 : w0);
#pragma unroll
            for (int nt = 0; nt < 8; nt++) {
                unsigned b0 = Vb[(j * 8 + tg) * KSTR + nt * 8 + gid];
                unsigned b1 = Vb[(j * 8 + tg + 4) * KSTR + nt * 8 + gid];
                mma8(o[nt], pa0, pa1, pa2, pa3, b0, b1);
            }
        }
        __syncthreads();
    }

    // Epilogue: store UNNORMALIZED partial O + per-row (m, l)
    const int rowb = b * SEQ + qt * 64 + warp * 16;
    const size_t obase = ((size_t)sp * MTOT + rowb) * DK;
#pragma unroll
    for (int nt = 0; nt < 8; nt++) {
        const int col = nt * 8 + tg * 2;
        *(float2*)&g_op[obase + (size_t)gid * DK + col] =
            make_float2(o[nt][0], o[nt][1]);
        *(float2*)&g_op[obase + (size_t)(gid + 8) * DK + col] =
            make_float2(o[nt][2], o[nt][3]);
    }
    if (tg == 0) {
        g_ms[sp * MTOT + rowb + gid]     = m0;
        g_ls[sp * MTOT + rowb + gid]     = l0;
        g_ms[sp * MTOT + rowb + gid + 8] = m1;
        g_ls[sp * MTOT + rowb + gid + 8] = l1;
    }
}

// ---------------------------------------------------------------------------
// Combine the SPLIT partials (vectorized float4).
// ---------------------------------------------------------------------------
__global__ __launch_bounds__(256) void combine_kernel(float* __restrict__ out)
{
    const int v = blockIdx.x * 256 + threadIdx.x;   // float4 idx over MTOT*DK/4
    const int row = v >> 4;                          // 16 float4 per row

    float mv[SPLIT];
    float M = -1e30f;
#pragma unroll
    for (int i = 0; i < SPLIT; i++) {
        mv[i] = g_ms[i * MTOT + row];
        M = fmaxf(M, mv[i]);
    }
    float L = 0.0f;
    float4 acc = make_float4(0.0f, 0.0f, 0.0f, 0.0f);
#pragma unroll
    for (int i = 0; i < SPLIT; i++) {
        const float w = __expf(mv[i] - M);
        L += g_ls[i * MTOT + row] * w;
        float4 p = *(const float4*)&g_op[(size_t)i * MTOT * DK + (size_t)v * 4];
        acc.x += p.x * w; acc.y += p.y * w;
        acc.z += p.z * w; acc.w += p.w * w;
    }
    const float inv = 1.0f / L;
    *(float4*)&out[(size_t)v * 4] =
        make_float4(acc.x * inv, acc.y * inv, acc.z * inv, acc.w * inv);
}

// ---------------------------------------------------------------------------
extern "C" void kernel_launch(void* const* d_in, const int* in_sizes, int n_in,
                              void* d_out, int out_size)
{
    const float* q_in = (const float*)d_in[0];
    const float* k_in = (const float*)d_in[1];
    const float* v_in = (const float*)d_in[2];
    const float* Wq   = (const float*)d_in[3];
    const float* bq   = (const float*)d_in[4];
    const float* Wk   = (const float*)d_in[5];
    const float* bk   = (const float*)d_in[6];
    const float* Wv   = (const float*)d_in[7];
    const float* bv   = (const float*)d_in[8];
    float* out = (float*)d_out;

    const int proj_smem = (2 * 128 * XSP + 2 * 64 * WSP) * 4;   // 106,496
    const int attn_smem = 4 * 64 * KSTR * 4;                     // 73,728
    static int attr_set = 0;
    if (!attr_set) {
        cudaFuncSetAttribute(proj_mma,
                             cudaFuncAttributeMaxDynamicSharedMemorySize, proj_smem);
        cudaFuncSetAttribute(attn_mma,
                             cudaFuncAttributeMaxDynamicSharedMemorySize, attn_smem);
        attr_set = 1;
    }

    convert_w<<<96, 256>>>(Wq, Wk, Wv);

    dim3 pgrid(MTOT / 128, 3);
    proj_mma<<<pgrid, 256, proj_smem>>>(q_in, k_in, v_in, bq, bk, bv);

    dim3 agrid(SEQ / 64, NB, SPLIT);
    attn_mma<<<agrid, 128, attn_smem>>>();

    combine_kernel<<<MTOT * DK / 1024, 256>>>(out);
}